// round 2
// baseline (speedup 1.0000x reference)
#include <cuda_runtime.h>
#include <cuda_bf16.h>
#include <math.h>

// DynamicRouter: logits = x @ W^T + b + 0.1*noise ; top-2 ; sparse softmax.
// x[B=8,S=4096,D=768] f32, W[E=8,D=768] f32, b[8] f32, noise[B,S,8] f32.
// out: router_output [B,S,8] f32 (+ optionally top_k_indices [B,S,2] as f32).

#define D_DIM        768
#define E_DIM        8
#define TOK_PER_WARP 4
#define WARPS        8
#define BLOCK        (WARPS * 32)
#define TOK_PER_BLK  (WARPS * TOK_PER_WARP)   // 32
#define D4           (D_DIM / 4)              // 192
#define NOISE_STD    0.1f

__global__ __launch_bounds__(BLOCK)
void router_kernel(const float* __restrict__ x,
                   const float* __restrict__ W,
                   const float* __restrict__ b,
                   const float* __restrict__ noise,
                   float* __restrict__ out,
                   int nTokens, int writeIdx)
{
    __shared__ float sW[E_DIM * D_DIM];   // 24 KB

    const int tid  = threadIdx.x;
    const int lane = tid & 31;
    const int wid  = tid >> 5;

    // Stage W into shared (coalesced float4 copy; W is contiguous 24 KB)
    {
        const float4* Wg = reinterpret_cast<const float4*>(W);
        float4*       Ws = reinterpret_cast<float4*>(sW);
        #pragma unroll
        for (int i = 0; i < (E_DIM * D4) / BLOCK; i++)
            Ws[i * BLOCK + tid] = Wg[i * BLOCK + tid];
    }
    __syncthreads();

    const int tokBase = blockIdx.x * TOK_PER_BLK + wid * TOK_PER_WARP;
    if (tokBase >= nTokens) return;

    const float4* x4  = reinterpret_cast<const float4*>(x) + (size_t)tokBase * D4;
    const float4* sW4 = reinterpret_cast<const float4*>(sW);

    // acc[t*8+e] : token t (0..3) x expert e (0..7)
    float acc[TOK_PER_WARP * E_DIM];
    #pragma unroll
    for (int v = 0; v < TOK_PER_WARP * E_DIM; v++) acc[v] = 0.0f;

    // Main loop: 6 chunks of 32 float4 positions; each lane owns position i*32+lane.
    // unroll 2: ~48 outstanding LDG.128 worth of MLP without register spill.
    #pragma unroll 2
    for (int i = 0; i < D4 / 32; i++) {
        const int p = i * 32 + lane;
        float4 xv[TOK_PER_WARP];
        #pragma unroll
        for (int t = 0; t < TOK_PER_WARP; t++)
            xv[t] = x4[(size_t)t * D4 + p];           // coalesced 512B per token
        #pragma unroll
        for (int e = 0; e < E_DIM; e++) {
            const float4 wv = sW4[e * D4 + p];        // LDS.128, reused for 4 tokens
            #pragma unroll
            for (int t = 0; t < TOK_PER_WARP; t++) {
                acc[t * E_DIM + e] += xv[t].x * wv.x + xv[t].y * wv.y
                                    + xv[t].z * wv.z + xv[t].w * wv.w;
            }
        }
    }

    // Log-halving butterfly reduction: 31 shuffles total.
    // After step with mask m, lanes with (lane&m)==0 keep value-indices [0,m),
    // upper lanes keep [m,2m) re-indexed to [0,m). By induction lane l ends
    // holding the complete 32-lane sum for value index v == l.
    #pragma unroll
    for (int m = 16; m >= 1; m >>= 1) {
        const bool upper = (lane & m) != 0;
        #pragma unroll
        for (int i = 0; i < m; i++) {
            const float lo = acc[i], hi = acc[i + m];
            const float send = upper ? lo : hi;
            const float recv = __shfl_xor_sync(0xFFFFFFFFu, send, m);
            acc[i] = upper ? (hi + recv) : (lo + recv);
        }
    }
    const float sum = acc[0];

    // lane l -> token t = l>>3 (within warp group), expert e = l&7
    const int t = lane >> 3;
    const int e = lane & 7;
    const long tok = (long)tokBase + t;

    // noise read: lane l reads noise[tokBase*8 + l] -> contiguous 128B/warp
    const float logit = sum + __ldg(b + e)
                      + NOISE_STD * __ldg(noise + (size_t)tokBase * E_DIM + lane);

    // top-1 over the 8-lane expert group (higher value wins; ties -> lower index,
    // matching jax.lax.top_k semantics)
    float v1 = logit; int i1 = e;
    #pragma unroll
    for (int off = 1; off < 8; off <<= 1) {
        const float ov = __shfl_xor_sync(0xFFFFFFFFu, v1, off);
        const int   oi = __shfl_xor_sync(0xFFFFFFFFu, i1, off);
        if (ov > v1 || (ov == v1 && oi < i1)) { v1 = ov; i1 = oi; }
    }
    // top-2: exclude winner, reduce again
    float v2 = (e == i1) ? -INFINITY : logit; int i2 = e;
    #pragma unroll
    for (int off = 1; off < 8; off <<= 1) {
        const float ov = __shfl_xor_sync(0xFFFFFFFFu, v2, off);
        const int   oi = __shfl_xor_sync(0xFFFFFFFFu, i2, off);
        if (ov > v2 || (ov == v2 && oi < i2)) { v2 = ov; i2 = oi; }
    }

    // softmax over {-inf except top2}: p1 = 1/(1+exp(v2-v1)), p2 = exp(v2-v1)*p1
    const float ed  = __expf(v2 - v1);        // v2 <= v1, so arg <= 0: no overflow
    const float inv = 1.0f / (1.0f + ed);
    const float p   = (e == i1) ? inv : ((e == i2) ? ed * inv : 0.0f);

    // coalesced 128B write per warp
    out[(size_t)tokBase * E_DIM + lane] = p;

    if (writeIdx && e == 0) {
        float* idxOut = out + (size_t)nTokens * E_DIM;
        idxOut[tok * 2 + 0] = (float)i1;
        idxOut[tok * 2 + 1] = (float)i2;
    }
}

extern "C" void kernel_launch(void* const* d_in, const int* in_sizes, int n_in,
                              void* d_out, int out_size)
{
    const float* x     = (const float*)d_in[0];
    const float* W     = (const float*)d_in[1];
    const float* b     = (const float*)d_in[2];
    const float* noise = (const float*)d_in[3];
    float* out = (float*)d_out;

    const int nTokens = in_sizes[3] / E_DIM;          // B*S from noise elem count
    const int writeIdx = (out_size >= nTokens * E_DIM + nTokens * 2) ? 1 : 0;

    const int grid = (nTokens + TOK_PER_BLK - 1) / TOK_PER_BLK;
    router_kernel<<<grid, BLOCK>>>(x, W, b, noise, out, nTokens, writeIdx);
}